// round 1
// baseline (speedup 1.0000x reference)
#include <cuda_runtime.h>

// Problem: RetrieverListwiseHardNegLoss — listwise segment-LSE loss + pairwise
// hard-negative softplus loss over G=4096 graphs x L=512 edges.
//
// Inputs (metadata order): logits f32[E], targets f32[E], edge_batch i32[E] (UNUSED
// — segments are equal-size contiguous by construction), num_graphs (scalar, unused;
// G derived as E/512). Output: f32[1] scalar loss.

#define NEGV (-1e30f)

static constexpr int LLEN  = 512;          // edges per graph
static constexpr int KSEL  = 32;           // hard-negative k
static constexpr int NWARP = LLEN / 32;    // 16 warps per block

// Per-graph partials: (listwise_term, has_pos, pairwise_contrib, active)
__device__ float4 g_part[8192];

__global__ __launch_bounds__(LLEN) void rll_main(const float* __restrict__ logits,
                                                 const float* __restrict__ targets) {
    const int g    = blockIdx.x;
    const int tid  = threadIdx.x;
    const int lane = tid & 31;
    const int wid  = tid >> 5;

    const size_t base = (size_t)g * LLEN;
    const float l   = logits[base + tid];
    const bool  pos = targets[base + tid] > 0.5f;
    const float s   = l * 10.0f;  // logits / TEMPERATURE(0.1)

    __shared__ float sh_a[NWARP];
    __shared__ float sh_b[NWARP];
    __shared__ int   sh_wpc[NWARP];
    __shared__ float sh_bc[2];
    __shared__ float sh_sorted[LLEN];
    __shared__ float sh_hard[KSEL];
    __shared__ float sh_plog[LLEN];

    // ---------- Phase 1: block maxima (all / positives) ----------
    float ma = s;
    float mp = pos ? s : NEGV;
    #pragma unroll
    for (int j = 16; j; j >>= 1) {
        ma = fmaxf(ma, __shfl_xor_sync(0xffffffffu, ma, j));
        mp = fmaxf(mp, __shfl_xor_sync(0xffffffffu, mp, j));
    }
    if (lane == 0) { sh_a[wid] = ma; sh_b[wid] = mp; }
    __syncthreads();
    if (tid == 0) {
        float A = sh_a[0], B = sh_b[0];
        #pragma unroll
        for (int w = 1; w < NWARP; w++) { A = fmaxf(A, sh_a[w]); B = fmaxf(B, sh_b[w]); }
        sh_bc[0] = A; sh_bc[1] = B;
    }
    __syncthreads();
    const float m_all = sh_bc[0];
    const float m_pos = sh_bc[1];

    // ---------- Phase 2: exp-sums + positive count ----------
    float ea = expf(s - m_all);
    float ep = pos ? expf(s - m_pos) : 0.0f;
    const unsigned bal = __ballot_sync(0xffffffffu, pos);
    #pragma unroll
    for (int j = 16; j; j >>= 1) {
        ea += __shfl_xor_sync(0xffffffffu, ea, j);
        ep += __shfl_xor_sync(0xffffffffu, ep, j);
    }
    if (lane == 0) { sh_a[wid] = ea; sh_b[wid] = ep; sh_wpc[wid] = __popc(bal); }
    __syncthreads();

    // All threads: total positives P and this warp's compaction offset (deterministic).
    int P = 0, woff = 0;
    #pragma unroll
    for (int w = 0; w < NWARP; w++) {
        int c = sh_wpc[w];
        if (w < wid) woff += c;
        P += c;
    }
    const int kg = min(LLEN - P, KSEL);

    float sum_all = 0.0f, sum_pos = 0.0f;
    if (tid == 0) {
        #pragma unroll
        for (int w = 0; w < NWARP; w++) { sum_all += sh_a[w]; sum_pos += sh_b[w]; }
    }

    // ---------- Phase 3: per-warp bitonic sort of negatives (registers) ----------
    float v = pos ? NEGV : l;
    #pragma unroll
    for (int k = 2; k <= 32; k <<= 1) {
        #pragma unroll
        for (int j = k >> 1; j > 0; j >>= 1) {
            float o = __shfl_xor_sync(0xffffffffu, v, j);
            bool up      = ((lane & k) == 0);
            bool lowlane = ((lane & j) == 0);
            v = (up == lowlane) ? fminf(v, o) : fmaxf(v, o);
        }
    }
    // v is ascending by lane -> store descending
    sh_sorted[(wid << 5) + lane] = __shfl_sync(0xffffffffu, v, 31 - lane);

    // Compact positive logits into sh_plog with deterministic ranks.
    if (pos) {
        int rank = woff + __popc(bal & ((1u << lane) - 1u));
        sh_plog[rank] = l;
    }
    __syncthreads();

    // ---------- Phase 4: warp 0 merges 16 desc-sorted lists -> global top-32 ----------
    if (wid == 0) {
        float a = sh_sorted[lane];
        #pragma unroll
        for (int w = 1; w < NWARP; w++) {
            float b = sh_sorted[(w << 5) + (31 - lane)];   // reversed -> bitonic combine
            a = fmaxf(a, b);
            #pragma unroll
            for (int j = 16; j; j >>= 1) {                 // bitonic merge, descending
                float o = __shfl_xor_sync(0xffffffffu, a, j);
                bool lowlane = ((lane & j) == 0);
                a = lowlane ? fmaxf(a, o) : fminf(a, o);
            }
        }
        sh_hard[lane] = a;  // top-32 descending; entries >= kg never read below
    }
    __syncthreads();

    // ---------- Phase 5: pairwise softplus over P x kg pairs ----------
    float psum = 0.0f;
    const int pairs = P * kg;
    for (int idx = tid; idx < pairs; idx += LLEN) {
        int p = idx / kg;
        int n = idx - p * kg;
        float x = 0.5f + sh_hard[n] - sh_plog[p];          // MARGIN + hard_n - logit_p
        psum += fmaxf(x, 0.0f) + log1pf(expf(-fabsf(x)));  // stable softplus
    }
    #pragma unroll
    for (int j = 16; j; j >>= 1) psum += __shfl_xor_sync(0xffffffffu, psum, j);
    if (lane == 0) sh_a[wid] = psum;
    __syncthreads();

    if (tid == 0) {
        float pt = 0.0f;
        #pragma unroll
        for (int w = 0; w < NWARP; w++) pt += sh_a[w];

        float log_denom = m_all + logf(sum_all);
        bool  has_pos   = (P > 0);
        float lw = 0.0f;
        if (has_pos) lw = log_denom - (m_pos + logf(sum_pos));  // -(log_num - log_denom)
        bool  active  = has_pos && (kg > 0);
        float contrib = active ? pt / fmaxf((float)P * (float)kg, 1.0f) : 0.0f;
        g_part[g] = make_float4(lw, has_pos ? 1.0f : 0.0f, contrib, active ? 1.0f : 0.0f);
    }
}

__global__ __launch_bounds__(512) void rll_final(float* __restrict__ out, int G) {
    __shared__ float sh[4][NWARP];
    const int tid = threadIdx.x, lane = tid & 31, wid = tid >> 5;
    float slw = 0.0f, chp = 0.0f, spw = 0.0f, cac = 0.0f;
    for (int i = tid; i < G; i += 512) {
        float4 vv = g_part[i];
        slw += vv.x; chp += vv.y; spw += vv.z; cac += vv.w;
    }
    #pragma unroll
    for (int j = 16; j; j >>= 1) {
        slw += __shfl_xor_sync(0xffffffffu, slw, j);
        chp += __shfl_xor_sync(0xffffffffu, chp, j);
        spw += __shfl_xor_sync(0xffffffffu, spw, j);
        cac += __shfl_xor_sync(0xffffffffu, cac, j);
    }
    if (lane == 0) { sh[0][wid] = slw; sh[1][wid] = chp; sh[2][wid] = spw; sh[3][wid] = cac; }
    __syncthreads();
    if (tid == 0) {
        float a = 0, b = 0, c = 0, d = 0;
        #pragma unroll
        for (int w = 0; w < NWARP; w++) { a += sh[0][w]; b += sh[1][w]; c += sh[2][w]; d += sh[3][w]; }
        // LISTWISE_W * listwise + PAIRWISE_W * pairwise
        out[0] = a / fmaxf(b, 1.0f) + 0.5f * (c / fmaxf(d, 1.0f));
    }
}

extern "C" void kernel_launch(void* const* d_in, const int* in_sizes, int n_in,
                              void* d_out, int out_size) {
    const float* logits  = (const float*)d_in[0];
    const float* targets = (const float*)d_in[1];
    // d_in[2] (edge_batch) and d_in[3] (num_graphs) unused: segments are
    // equal-size contiguous by construction.
    const int E = in_sizes[0];
    const int G = E / LLEN;

    rll_main<<<G, LLEN>>>(logits, targets);
    rll_final<<<1, 512>>>((float*)d_out, G);
}

// round 2
// speedup vs baseline: 1.7213x; 1.7213x over previous
#include <cuda_runtime.h>

// RetrieverListwiseHardNegLoss — warp-per-graph, fully warp-synchronous.
// G graphs x L=512 edges, contiguous equal segments (edge_batch unused).
// Each warp owns one graph: 16 elements per lane, all reductions via shuffles,
// top-32 via per-lane register bitonic sort + 32-pop shuffle tournament.
// Final scalar reduction folded into the last-finishing block (atomic counter).

#define FULL 0xffffffffu
#define NEGV (-1e30f)

static constexpr int LLEN = 512;   // edges per graph
static constexpr int WPB  = 8;     // warps (graphs) per block
static constexpr int TPB  = WPB * 32;

__device__ float4   g_part[8192];  // (listwise_term, has_pos, contrib, active)
__device__ unsigned g_ctr = 0;

__device__ __forceinline__ float warp_max(float v) {
    #pragma unroll
    for (int j = 16; j; j >>= 1) v = fmaxf(v, __shfl_xor_sync(FULL, v, j));
    return v;
}
__device__ __forceinline__ float warp_sum(float v) {
    #pragma unroll
    for (int j = 16; j; j >>= 1) v += __shfl_xor_sync(FULL, v, j);
    return v;
}
__device__ __forceinline__ int warp_isum(int v) {
    #pragma unroll
    for (int j = 16; j; j >>= 1) v += __shfl_xor_sync(FULL, v, j);
    return v;
}

__global__ __launch_bounds__(TPB) void rll_fused(const float* __restrict__ logits,
                                                 const float* __restrict__ targets,
                                                 float* __restrict__ out,
                                                 int G, int nblk) {
    const int lane = threadIdx.x & 31;
    const int wid  = threadIdx.x >> 5;
    const int g    = blockIdx.x * WPB + wid;

    __shared__ float sm[WPB][32 * 17];   // padded: stride 17 -> conflict-free
    __shared__ bool  s_last;
    __shared__ float s_red[4][WPB];

    if (g < G) {
        // ---- coalesced vector loads: instr q covers 128 consecutive float4 ----
        const float4* L4 = (const float4*)(logits  + (size_t)g * LLEN);
        const float4* T4 = (const float4*)(targets + (size_t)g * LLEN);
        float l[16];
        unsigned pm = 0;                 // per-lane positive mask (16 bits)
        #pragma unroll
        for (int q = 0; q < 4; q++) {
            float4 a = L4[q * 32 + lane];
            float4 t = T4[q * 32 + lane];
            l[q*4+0] = a.x; l[q*4+1] = a.y; l[q*4+2] = a.z; l[q*4+3] = a.w;
            pm |= (t.x > 0.5f ? 1u : 0u) << (q*4+0);
            pm |= (t.y > 0.5f ? 1u : 0u) << (q*4+1);
            pm |= (t.z > 0.5f ? 1u : 0u) << (q*4+2);
            pm |= (t.w > 0.5f ? 1u : 0u) << (q*4+3);
        }

        // ---- maxima on raw logits (scaling by 10 is monotone) ----
        float ma = NEGV, mp = NEGV;
        #pragma unroll
        for (int i = 0; i < 16; i++) {
            ma = fmaxf(ma, l[i]);
            mp = fmaxf(mp, ((pm >> i) & 1) ? l[i] : NEGV);
        }
        ma = warp_max(ma);
        mp = warp_max(mp);

        // ---- exp sums (scaled logits: exp(10*(l - m))) ----
        float ea = 0.0f, ep = 0.0f;
        #pragma unroll
        for (int i = 0; i < 16; i++) {
            ea += __expf((l[i] - ma) * 10.0f);
            float t2 = __expf((l[i] - mp) * 10.0f);   // <=1 for positives
            ep += ((pm >> i) & 1) ? t2 : 0.0f;        // inf for negs discarded by select
        }
        ea = warp_sum(ea);
        ep = warp_sum(ep);
        const int P  = warp_isum(__popc(pm));
        const int kg = min(LLEN - P, 32);

        // ---- per-lane bitonic sort (descending) of 16 negatives, in registers ----
        float w[16];
        #pragma unroll
        for (int i = 0; i < 16; i++) w[i] = ((pm >> i) & 1) ? NEGV : l[i];
        #pragma unroll
        for (int k = 2; k <= 16; k <<= 1) {
            #pragma unroll
            for (int j = k >> 1; j > 0; j >>= 1) {
                #pragma unroll
                for (int i = 0; i < 16; i++) {
                    int x = i ^ j;
                    if (x > i) {
                        bool dir = ((i & k) == 0);   // final merge (k=16) -> descending
                        float lo = fminf(w[i], w[x]), hi = fmaxf(w[i], w[x]);
                        w[i] = dir ? hi : lo;
                        w[x] = dir ? lo : hi;
                    }
                }
            }
        }
        float* my = &sm[wid][lane * 17];
        #pragma unroll
        for (int i = 0; i < 16; i++) my[i] = w[i];
        my[16] = NEGV;                    // sentinel: lane can be popped <=16 times
        __syncwarp();

        // ---- tournament: pop global max 32 times; lane n ends with n-th largest ----
        float head = my[0];
        int   ptr  = 0;
        float hard = NEGV;
        #pragma unroll 1
        for (int it = 0; it < 32; ++it) {
            float m = warp_max(head);
            unsigned b = __ballot_sync(FULL, head == m);
            int src = __ffs(b) - 1;
            if (lane == it)  hard = m;
            if (lane == src) { ptr++; head = my[ptr]; }
        }

        // ---- pairwise softplus: broadcast each positive, lanes are negatives ----
        float psum = 0.0f;
        #pragma unroll
        for (int r = 0; r < 16; r++) {
            unsigned bal = __ballot_sync(FULL, (pm >> r) & 1);
            while (bal) {
                int src = __ffs(bal) - 1;
                bal &= bal - 1;
                float lp = __shfl_sync(FULL, l[r], src);
                float x  = 0.5f + hard - lp;                       // MARGIN + h_n - l_p
                float sp = fmaxf(x, 0.0f) + __logf(1.0f + __expf(-fabsf(x)));
                if (lane < kg) psum += sp;
            }
        }
        psum = warp_sum(psum);

        if (lane == 0) {
            float log_den = ma * 10.0f + __logf(ea);
            bool  hasp    = (P > 0);
            float lw      = hasp ? (log_den - (mp * 10.0f + __logf(ep))) : 0.0f;
            bool  act     = hasp && (kg > 0);
            float contrib = act ? psum / fmaxf((float)P * (float)kg, 1.0f) : 0.0f;
            g_part[g] = make_float4(lw, hasp ? 1.0f : 0.0f, contrib, act ? 1.0f : 0.0f);
        }
    }

    // ---- last block reduces all per-graph partials (fixed order => deterministic) ----
    __syncthreads();
    __threadfence();
    if (threadIdx.x == 0)
        s_last = (atomicAdd(&g_ctr, 1u) == (unsigned)(nblk - 1));
    __syncthreads();
    if (s_last) {
        float a = 0, b = 0, c = 0, d = 0;
        for (int i = threadIdx.x; i < G; i += TPB) {
            float4 v = g_part[i];
            a += v.x; b += v.y; c += v.z; d += v.w;
        }
        a = warp_sum(a); b = warp_sum(b); c = warp_sum(c); d = warp_sum(d);
        if (lane == 0) { s_red[0][wid] = a; s_red[1][wid] = b; s_red[2][wid] = c; s_red[3][wid] = d; }
        __syncthreads();
        if (threadIdx.x == 0) {
            float A = 0, B = 0, C = 0, D = 0;
            #pragma unroll
            for (int v2 = 0; v2 < WPB; v2++) {
                A += s_red[0][v2]; B += s_red[1][v2];
                C += s_red[2][v2]; D += s_red[3][v2];
            }
            out[0] = A / fmaxf(B, 1.0f) + 0.5f * (C / fmaxf(D, 1.0f));
            g_ctr = 0;                   // reset for next graph replay
        }
    }
}

extern "C" void kernel_launch(void* const* d_in, const int* in_sizes, int n_in,
                              void* d_out, int out_size) {
    const float* logits  = (const float*)d_in[0];
    const float* targets = (const float*)d_in[1];
    // d_in[2] (edge_batch) / d_in[3] (num_graphs) unused: segments are
    // equal-size (512) contiguous by construction.
    const int E = in_sizes[0];
    const int G = E / LLEN;
    const int nblk = (G + WPB - 1) / WPB;

    rll_fused<<<nblk, TPB>>>(logits, targets, (float*)d_out, G, nblk);
}

// round 3
// speedup vs baseline: 2.8000x; 1.6267x over previous
#include <cuda_runtime.h>

// RetrieverListwiseHardNegLoss — warp-per-graph, fully warp-synchronous.
// R3: tournament -> bitonic row-sort + merge tree (throughput, not latency);
//     pairwise while(ballot) -> smem-compacted positives, fixed-trip loop;
//     launch_bounds(256,4) -> single wave.

#define FULL 0xffffffffu
#define NEGV (-1e30f)

static constexpr int LLEN = 512;   // edges per graph
static constexpr int WPB  = 8;     // warps (graphs) per block
static constexpr int TPB  = WPB * 32;

__device__ float4   g_part[8192];  // (listwise_term, has_pos, contrib, active)
__device__ unsigned g_ctr = 0;

__device__ __forceinline__ float warp_max(float v) {
    #pragma unroll
    for (int j = 16; j; j >>= 1) v = fmaxf(v, __shfl_xor_sync(FULL, v, j));
    return v;
}
__device__ __forceinline__ float warp_sum(float v) {
    #pragma unroll
    for (int j = 16; j; j >>= 1) v += __shfl_xor_sync(FULL, v, j);
    return v;
}

// Merge two ascending sorted-32 warp lists; return ascending sorted top-32.
__device__ __forceinline__ float merge32(float a, float b, int lane) {
    float br = __shfl_sync(FULL, b, 31 - lane);
    float c  = fmaxf(a, br);              // top-32 multiset (bitonic order)
    #pragma unroll
    for (int j = 16; j; j >>= 1) {        // bitonic clean -> ascending
        float o = __shfl_xor_sync(FULL, c, j);
        c = ((lane & j) == 0) ? fminf(c, o) : fmaxf(c, o);
    }
    return c;
}

__global__ __launch_bounds__(TPB, 4) void rll_fused(const float* __restrict__ logits,
                                                    const float* __restrict__ targets,
                                                    float* __restrict__ out,
                                                    int G, int nblk) {
    const int lane = threadIdx.x & 31;
    const int wid  = threadIdx.x >> 5;
    const int g    = blockIdx.x * WPB + wid;

    __shared__ float smp[WPB][LLEN];     // compacted positive logits per warp
    __shared__ bool  s_last;
    __shared__ float s_red[4][WPB];

    if (g < G) {
        // ---------- coalesced vector loads ----------
        const float4* L4 = (const float4*)(logits  + (size_t)g * LLEN);
        const float4* T4 = (const float4*)(targets + (size_t)g * LLEN);
        float l[16];
        unsigned pm = 0;                 // per-lane positive mask (16 bits)
        #pragma unroll
        for (int q = 0; q < 4; q++) {
            float4 a = L4[q * 32 + lane];
            float4 t = T4[q * 32 + lane];
            l[q*4+0] = a.x; l[q*4+1] = a.y; l[q*4+2] = a.z; l[q*4+3] = a.w;
            pm |= (t.x > 0.5f ? 1u : 0u) << (q*4+0);
            pm |= (t.y > 0.5f ? 1u : 0u) << (q*4+1);
            pm |= (t.z > 0.5f ? 1u : 0u) << (q*4+2);
            pm |= (t.w > 0.5f ? 1u : 0u) << (q*4+3);
        }

        // ---------- max over all, exp-sum over all (scaled by 10 = 1/T) ----------
        float ma = l[0];
        #pragma unroll
        for (int i = 1; i < 16; i++) ma = fmaxf(ma, l[i]);
        ma = warp_max(ma);
        float ea = 0.0f;
        #pragma unroll
        for (int i = 0; i < 16; i++) ea += __expf((l[i] - ma) * 10.0f);
        ea = warp_sum(ea);

        // ---------- compact positives into smem (deterministic ranks) ----------
        float* pl = smp[wid];
        int cnt = 0;
        #pragma unroll
        for (int i = 0; i < 16; i++) {
            unsigned bal = __ballot_sync(FULL, (pm >> i) & 1);
            if ((pm >> i) & 1)
                pl[cnt + __popc(bal & ((1u << lane) - 1u))] = l[i];
            cnt += __popc(bal);
        }
        const int P  = cnt;
        const int kg = min(LLEN - P, 32);
        __syncwarp();

        // ---------- positive max / exp-sum from compacted list ----------
        float mp = NEGV;
        for (int r = lane; r < P; r += 32) mp = fmaxf(mp, pl[r]);
        mp = warp_max(mp);
        float ep = 0.0f;
        for (int r = lane; r < P; r += 32) ep += __expf((pl[r] - mp) * 10.0f);
        ep = warp_sum(ep);

        // ---------- top-32 negatives: sort 16 rows asc across lanes ----------
        #pragma unroll
        for (int i = 0; i < 16; i++) l[i] = ((pm >> i) & 1) ? NEGV : l[i];
        #pragma unroll
        for (int k = 2; k <= 32; k <<= 1) {
            #pragma unroll
            for (int j = k >> 1; j; j >>= 1) {
                const bool keepmin = ((lane & j) == 0) == ((lane & k) == 0);
                #pragma unroll
                for (int i = 0; i < 16; i++) {
                    float o = __shfl_xor_sync(FULL, l[i], j);
                    l[i] = keepmin ? fminf(l[i], o) : fmaxf(l[i], o);
                }
            }
        }
        // ---------- merge tree: 16 -> 8 -> 4 -> 2 -> root (set only) ----------
        #pragma unroll
        for (int i = 0; i < 8; i++) l[i] = merge32(l[2*i], l[2*i+1], lane);
        #pragma unroll
        for (int i = 0; i < 4; i++) l[i] = merge32(l[2*i], l[2*i+1], lane);
        #pragma unroll
        for (int i = 0; i < 2; i++) l[i] = merge32(l[2*i], l[2*i+1], lane);
        const float hard = fmaxf(l[0], __shfl_sync(FULL, l[1], 31 - lane));
        // lane holds one member of the top-32 multiset; lanes beyond the
        // negative count hold NEGV -> softplus evaluates to exactly 0.

        // ---------- pairwise softplus: fixed-trip loop over positives ----------
        float psum = 0.0f;
        const float hb = 0.5f + hard;     // MARGIN + hard_n
        int p = 0;
        for (; p + 4 <= P; p += 4) {
            float4 q = *(const float4*)&pl[p];
            float x0 = hb - q.x, x1 = hb - q.y, x2 = hb - q.z, x3 = hb - q.w;
            psum += fmaxf(x0, 0.f) + __logf(1.f + __expf(-fabsf(x0)));
            psum += fmaxf(x1, 0.f) + __logf(1.f + __expf(-fabsf(x1)));
            psum += fmaxf(x2, 0.f) + __logf(1.f + __expf(-fabsf(x2)));
            psum += fmaxf(x3, 0.f) + __logf(1.f + __expf(-fabsf(x3)));
        }
        for (; p < P; p++) {
            float x = hb - pl[p];
            psum += fmaxf(x, 0.f) + __logf(1.f + __expf(-fabsf(x)));
        }
        psum = warp_sum(psum);

        if (lane == 0) {
            bool  hasp    = (P > 0);
            float lw      = hasp ? (10.0f * (ma - mp) + __logf(ea) - __logf(ep)) : 0.0f;
            bool  act     = hasp && (kg > 0);
            float contrib = act ? psum / fmaxf((float)P * (float)kg, 1.0f) : 0.0f;
            g_part[g] = make_float4(lw, hasp ? 1.0f : 0.0f, contrib, act ? 1.0f : 0.0f);
        }
    }

    // ---------- last block reduces per-graph partials (fixed order) ----------
    __syncthreads();
    __threadfence();
    if (threadIdx.x == 0)
        s_last = (atomicAdd(&g_ctr, 1u) == (unsigned)(nblk - 1));
    __syncthreads();
    if (s_last) {
        float a = 0, b = 0, c = 0, d = 0;
        for (int i = threadIdx.x; i < G; i += TPB) {
            float4 v = g_part[i];
            a += v.x; b += v.y; c += v.z; d += v.w;
        }
        a = warp_sum(a); b = warp_sum(b); c = warp_sum(c); d = warp_sum(d);
        if (lane == 0) { s_red[0][wid] = a; s_red[1][wid] = b; s_red[2][wid] = c; s_red[3][wid] = d; }
        __syncthreads();
        if (threadIdx.x == 0) {
            float A = 0, B = 0, C = 0, D = 0;
            #pragma unroll
            for (int w = 0; w < WPB; w++) {
                A += s_red[0][w]; B += s_red[1][w];
                C += s_red[2][w]; D += s_red[3][w];
            }
            out[0] = A / fmaxf(B, 1.0f) + 0.5f * (C / fmaxf(D, 1.0f));
            g_ctr = 0;   // reset for next replay
        }
    }
}

extern "C" void kernel_launch(void* const* d_in, const int* in_sizes, int n_in,
                              void* d_out, int out_size) {
    const float* logits  = (const float*)d_in[0];
    const float* targets = (const float*)d_in[1];
    // d_in[2] (edge_batch) / d_in[3] (num_graphs) unused: segments are
    // equal-size (512) contiguous by construction.
    const int E = in_sizes[0];
    const int G = E / LLEN;
    const int nblk = (G + WPB - 1) / WPB;

    rll_fused<<<nblk, TPB>>>(logits, targets, (float*)d_out, G, nblk);
}

// round 4
// speedup vs baseline: 2.9682x; 1.0601x over previous
#include <cuda_runtime.h>

// RetrieverListwiseHardNegLoss — warp-per-graph, fully warp-synchronous.
// R4: per-lane Batcher halver + 8-row cross-lane sort with exact-threshold
//     fast path (fallback merges bottom rows; provably exact incl. ties);
//     single-pass LSE and softplus in log2 domain via raw EX2/LG2.

#define FULL 0xffffffffu
#define NEGV (-1e30f)

static constexpr int LLEN = 512;   // edges per graph
static constexpr int WPB  = 8;     // warps (graphs) per block
static constexpr int TPB  = WPB * 32;

static constexpr float LN2    = 0.6931471805599453f;
static constexpr float INVLN2 = 1.4426950408889634f;
static constexpr float KSC    = 14.426950408889634f;  // 10 / ln(2)

__device__ float4   g_part[8192];  // (listwise_term, has_pos, contrib, active)
__device__ unsigned g_ctr = 0;

__device__ __forceinline__ float ex2f_(float x) { float r; asm("ex2.approx.f32 %0, %1;" : "=f"(r) : "f"(x)); return r; }
__device__ __forceinline__ float lg2f_(float x) { float r; asm("lg2.approx.f32 %0, %1;" : "=f"(r) : "f"(x)); return r; }

__device__ __forceinline__ float warp_max(float v) {
    #pragma unroll
    for (int j = 16; j; j >>= 1) v = fmaxf(v, __shfl_xor_sync(FULL, v, j));
    return v;
}
__device__ __forceinline__ float warp_sum(float v) {
    #pragma unroll
    for (int j = 16; j; j >>= 1) v += __shfl_xor_sync(FULL, v, j);
    return v;
}

// Merge two ascending sorted-32 warp lists -> ascending sorted top-32.
__device__ __forceinline__ float merge32(float a, float b, int lane) {
    float br = __shfl_sync(FULL, b, 31 - lane);
    float c  = fmaxf(a, br);
    #pragma unroll
    for (int j = 16; j; j >>= 1) {
        float o = __shfl_xor_sync(FULL, c, j);
        c = ((lane & j) == 0) ? fminf(c, o) : fmaxf(c, o);
    }
    return c;
}

__device__ __forceinline__ void ce(float& a, float& b) {
    float lo = fminf(a, b), hi = fmaxf(a, b); a = lo; b = hi;
}
// Batcher odd-even mergesort, 8 inputs ascending (19 CE).
__device__ __forceinline__ void sort8(float* w) {
    ce(w[0],w[1]); ce(w[2],w[3]); ce(w[4],w[5]); ce(w[6],w[7]);
    ce(w[0],w[2]); ce(w[1],w[3]); ce(w[4],w[6]); ce(w[5],w[7]);
    ce(w[1],w[2]); ce(w[5],w[6]);
    ce(w[0],w[4]); ce(w[1],w[5]); ce(w[2],w[6]); ce(w[3],w[7]);
    ce(w[2],w[4]); ce(w[3],w[5]);
    ce(w[1],w[2]); ce(w[3],w[4]); ce(w[5],w[6]);
}
// Full bitonic sort of 8 rows across lanes (ascending per row).
__device__ __forceinline__ void rowsort8(float* w, int lane) {
    #pragma unroll
    for (int k = 2; k <= 32; k <<= 1) {
        #pragma unroll
        for (int j = k >> 1; j; j >>= 1) {
            const bool keepmin = ((lane & j) == 0) == ((lane & k) == 0);
            #pragma unroll
            for (int i = 0; i < 8; i++) {
                float o = __shfl_xor_sync(FULL, w[i], j);
                w[i] = keepmin ? fminf(w[i], o) : fmaxf(w[i], o);
            }
        }
    }
}
// 8 ascending sorted-32 lists -> ascending sorted global top-32.
__device__ __forceinline__ float mergetree8(float* w, int lane) {
    w[0] = merge32(w[0], w[1], lane); w[1] = merge32(w[2], w[3], lane);
    w[2] = merge32(w[4], w[5], lane); w[3] = merge32(w[6], w[7], lane);
    w[0] = merge32(w[0], w[1], lane); w[1] = merge32(w[2], w[3], lane);
    return merge32(w[0], w[1], lane);
}

__global__ __launch_bounds__(TPB, 4) void rll_fused(const float* __restrict__ logits,
                                                    const float* __restrict__ targets,
                                                    float* __restrict__ out,
                                                    int G, int nblk) {
    const int lane = threadIdx.x & 31;
    const int wid  = threadIdx.x >> 5;
    const int g    = blockIdx.x * WPB + wid;

    __shared__ float smp[WPB][LLEN];     // compacted positive logits per warp
    __shared__ bool  s_last;
    __shared__ float s_red[4][WPB];

    if (g < G) {
        // ---------- coalesced vector loads ----------
        const float4* L4 = (const float4*)(logits  + (size_t)g * LLEN);
        const float4* T4 = (const float4*)(targets + (size_t)g * LLEN);
        float w[16];
        unsigned pm = 0;                 // per-lane positive mask (16 bits)
        #pragma unroll
        for (int q = 0; q < 4; q++) {
            float4 a = L4[q * 32 + lane];
            float4 t = T4[q * 32 + lane];
            w[q*4+0] = a.x; w[q*4+1] = a.y; w[q*4+2] = a.z; w[q*4+3] = a.w;
            pm |= (t.x > 0.5f ? 1u : 0u) << (q*4+0);
            pm |= (t.y > 0.5f ? 1u : 0u) << (q*4+1);
            pm |= (t.z > 0.5f ? 1u : 0u) << (q*4+2);
            pm |= (t.w > 0.5f ? 1u : 0u) << (q*4+3);
        }

        // ---------- single-pass LSE (log2 domain, scale K = 10/ln2) ----------
        float ma = w[0];
        #pragma unroll
        for (int i = 1; i < 16; i++) ma = fmaxf(ma, w[i]);
        ma = warp_max(ma);
        const float maK = ma * KSC;
        float ea = 0.0f, ep = 0.0f;
        #pragma unroll
        for (int i = 0; i < 16; i++) {
            float e = ex2f_(fmaf(w[i], KSC, -maK));
            ea += e;
            ep += ((pm >> i) & 1) ? e : 0.0f;
        }
        ea = warp_sum(ea);
        ep = warp_sum(ep);

        // ---------- compact positives into smem (deterministic ranks) ----------
        float* pl = smp[wid];
        int cnt = 0;
        #pragma unroll
        for (int i = 0; i < 16; i++) {
            unsigned bal = __ballot_sync(FULL, (pm >> i) & 1);
            if ((pm >> i) & 1)
                pl[cnt + __popc(bal & ((1u << lane) - 1u))] = w[i];
            cnt += __popc(bal);
        }
        const int P  = cnt;
        const int kg = min(LLEN - P, 32);
        __syncwarp();

        // ---------- top-32 negatives ----------
        #pragma unroll
        for (int i = 0; i < 16; i++) w[i] = ((pm >> i) & 1) ? NEGV : w[i];
        // per-lane Batcher halver: top-8 multiset -> w[0..7], bottom -> w[8..15]
        sort8(w); sort8(w + 8);
        #pragma unroll
        for (int i = 0; i < 8; i++) ce(w[15 - i], w[i]);   // w[i]=max, w[15-i]=min
        float bmax = w[8];
        #pragma unroll
        for (int i = 9; i < 16; i++) bmax = fmaxf(bmax, w[i]);

        rowsort8(w, lane);
        float hard = mergetree8(w, lane);                  // candidate top-32, asc
        const float t = __shfl_sync(FULL, hard, 0);        // 32nd largest candidate
        if (__any_sync(FULL, bmax > t)) {                  // exact check (ties ok)
            rowsort8(w + 8, lane);
            float b32 = mergetree8(w + 8, lane);
            hard = fmaxf(hard, __shfl_sync(FULL, b32, 31 - lane));  // multiset
        }
        // lane beyond the negative count holds NEGV -> softplus contributes 0.

        // ---------- pairwise softplus in log2 domain ----------
        const float hbz = fmaf(hard, INVLN2, 0.5f * INVLN2);  // (0.5+hard)/ln2
        float zsum = 0.0f;
        int p = 0;
        for (; p + 4 <= P; p += 4) {
            float4 q = *(const float4*)&pl[p];
            #pragma unroll
            for (int u = 0; u < 4; u++) {
                float lp = (u == 0) ? q.x : (u == 1) ? q.y : (u == 2) ? q.z : q.w;
                float z  = fmaf(lp, -INVLN2, hbz);
                float e  = ex2f_(fminf(z, -z));            // 2^(-|z|)
                zsum += fmaxf(z, 0.0f) + lg2f_(1.0f + e);
            }
        }
        for (; p < P; p++) {
            float z = fmaf(pl[p], -INVLN2, hbz);
            float e = ex2f_(fminf(z, -z));
            zsum += fmaxf(z, 0.0f) + lg2f_(1.0f + e);
        }
        zsum = warp_sum(zsum);

        if (lane == 0) {
            bool  hasp    = (P > 0);
            float lw      = hasp ? LN2 * (lg2f_(ea) - lg2f_(ep)) : 0.0f;
            bool  act     = hasp && (kg > 0);
            float contrib = act ? (LN2 * zsum) / fmaxf((float)P * (float)kg, 1.0f) : 0.0f;
            g_part[g] = make_float4(lw, hasp ? 1.0f : 0.0f, contrib, act ? 1.0f : 0.0f);
        }
    }

    // ---------- last block reduces per-graph partials (fixed order) ----------
    __syncthreads();
    __threadfence();
    if (threadIdx.x == 0)
        s_last = (atomicAdd(&g_ctr, 1u) == (unsigned)(nblk - 1));
    __syncthreads();
    if (s_last) {
        float a = 0, b = 0, c = 0, d = 0;
        for (int i = threadIdx.x; i < G; i += TPB) {
            float4 v = g_part[i];
            a += v.x; b += v.y; c += v.z; d += v.w;
        }
        a = warp_sum(a); b = warp_sum(b); c = warp_sum(c); d = warp_sum(d);
        if (lane == 0) { s_red[0][wid] = a; s_red[1][wid] = b; s_red[2][wid] = c; s_red[3][wid] = d; }
        __syncthreads();
        if (threadIdx.x == 0) {
            float A = 0, B = 0, C = 0, D = 0;
            #pragma unroll
            for (int v2 = 0; v2 < WPB; v2++) {
                A += s_red[0][v2]; B += s_red[1][v2];
                C += s_red[2][v2]; D += s_red[3][v2];
            }
            out[0] = A / fmaxf(B, 1.0f) + 0.5f * (C / fmaxf(D, 1.0f));
            g_ctr = 0;   // reset for next replay
        }
    }
}

extern "C" void kernel_launch(void* const* d_in, const int* in_sizes, int n_in,
                              void* d_out, int out_size) {
    const float* logits  = (const float*)d_in[0];
    const float* targets = (const float*)d_in[1];
    // d_in[2] (edge_batch) / d_in[3] (num_graphs) unused: segments are
    // equal-size (512) contiguous by construction.
    const int E = in_sizes[0];
    const int G = E / LLEN;
    const int nblk = (G + WPB - 1) / WPB;

    rll_fused<<<nblk, TPB>>>(logits, targets, (float*)d_out, G, nblk);
}

// round 5
// speedup vs baseline: 3.1402x; 1.0579x over previous
#include <cuda_runtime.h>

// RetrieverListwiseHardNegLoss — warp-per-graph, fully warp-synchronous.
// R5: 5-inst softplus (no |z| fold, padded loop), FMA-chain positive mask +
//     scan-based compaction, ep from compacted list, hierarchical reduction.

#define FULL 0xffffffffu
#define NEGV (-1e30f)

static constexpr int LLEN = 512;   // edges per graph
static constexpr int WPB  = 8;     // warps (graphs) per block
static constexpr int TPB  = WPB * 32;

static constexpr float LN2    = 0.6931471805599453f;
static constexpr float INVLN2 = 1.4426950408889634f;
static constexpr float KSC    = 14.426950408889634f;  // 10 / ln(2)

__device__ float4   g_part[4096];  // per-BLOCK partials (nblk <= 4096)
__device__ unsigned g_ctr = 0;

__device__ __forceinline__ float ex2f_(float x) { float r; asm("ex2.approx.f32 %0, %1;" : "=f"(r) : "f"(x)); return r; }
__device__ __forceinline__ float lg2f_(float x) { float r; asm("lg2.approx.f32 %0, %1;" : "=f"(r) : "f"(x)); return r; }

__device__ __forceinline__ float warp_max(float v) {
    #pragma unroll
    for (int j = 16; j; j >>= 1) v = fmaxf(v, __shfl_xor_sync(FULL, v, j));
    return v;
}
__device__ __forceinline__ float warp_sum(float v) {
    #pragma unroll
    for (int j = 16; j; j >>= 1) v += __shfl_xor_sync(FULL, v, j);
    return v;
}

// Merge two ascending sorted-32 warp lists -> ascending sorted top-32.
__device__ __forceinline__ float merge32(float a, float b, int lane) {
    float br = __shfl_sync(FULL, b, 31 - lane);
    float c  = fmaxf(a, br);
    #pragma unroll
    for (int j = 16; j; j >>= 1) {
        float o = __shfl_xor_sync(FULL, c, j);
        c = ((lane & j) == 0) ? fminf(c, o) : fmaxf(c, o);
    }
    return c;
}

__device__ __forceinline__ void ce(float& a, float& b) {
    float lo = fminf(a, b), hi = fmaxf(a, b); a = lo; b = hi;
}
// Batcher odd-even mergesort, 8 inputs ascending (19 CE).
__device__ __forceinline__ void sort8(float* w) {
    ce(w[0],w[1]); ce(w[2],w[3]); ce(w[4],w[5]); ce(w[6],w[7]);
    ce(w[0],w[2]); ce(w[1],w[3]); ce(w[4],w[6]); ce(w[5],w[7]);
    ce(w[1],w[2]); ce(w[5],w[6]);
    ce(w[0],w[4]); ce(w[1],w[5]); ce(w[2],w[6]); ce(w[3],w[7]);
    ce(w[2],w[4]); ce(w[3],w[5]);
    ce(w[1],w[2]); ce(w[3],w[4]); ce(w[5],w[6]);
}
// Full bitonic sort of 8 rows across lanes (ascending per row).
__device__ __forceinline__ void rowsort8(float* w, int lane) {
    #pragma unroll
    for (int k = 2; k <= 32; k <<= 1) {
        #pragma unroll
        for (int j = k >> 1; j; j >>= 1) {
            const bool keepmin = ((lane & j) == 0) == ((lane & k) == 0);
            #pragma unroll
            for (int i = 0; i < 8; i++) {
                float o = __shfl_xor_sync(FULL, w[i], j);
                w[i] = keepmin ? fminf(w[i], o) : fmaxf(w[i], o);
            }
        }
    }
}
// 8 ascending sorted-32 lists -> ascending sorted global top-32.
__device__ __forceinline__ float mergetree8(float* w, int lane) {
    w[0] = merge32(w[0], w[1], lane); w[1] = merge32(w[2], w[3], lane);
    w[2] = merge32(w[4], w[5], lane); w[3] = merge32(w[6], w[7], lane);
    w[0] = merge32(w[0], w[1], lane); w[1] = merge32(w[2], w[3], lane);
    return merge32(w[0], w[1], lane);
}

__global__ __launch_bounds__(TPB, 4) void rll_fused(const float* __restrict__ logits,
                                                    const float* __restrict__ targets,
                                                    float* __restrict__ out,
                                                    int G, int nblk) {
    const int lane = threadIdx.x & 31;
    const int wid  = threadIdx.x >> 5;
    const int g    = blockIdx.x * WPB + wid;

    __shared__ float  smp[WPB][LLEN + 4];  // compacted positives + pad
    __shared__ float4 s_part[WPB];
    __shared__ bool   s_last;
    __shared__ float  s_red[4][WPB];

    float4 my_part = make_float4(0.f, 0.f, 0.f, 0.f);

    if (g < G) {
        // ---------- loads + FMA-chain positive mask (t in {0,1} exactly) ----------
        const float4* L4 = (const float4*)(logits  + (size_t)g * LLEN);
        const float4* T4 = (const float4*)(targets + (size_t)g * LLEN);
        float l[16];
        float pmf = 0.0f;
        #pragma unroll
        for (int q = 0; q < 4; q++) {
            float4 a = L4[q * 32 + lane];
            float4 t = T4[q * 32 + lane];
            l[q*4+0] = a.x; l[q*4+1] = a.y; l[q*4+2] = a.z; l[q*4+3] = a.w;
            pmf = fmaf(t.x, (float)(1u << (q*4+0)), pmf);
            pmf = fmaf(t.y, (float)(1u << (q*4+1)), pmf);
            pmf = fmaf(t.z, (float)(1u << (q*4+2)), pmf);
            pmf = fmaf(t.w, (float)(1u << (q*4+3)), pmf);
        }
        const unsigned pm = (unsigned)pmf;   // exact int <= 65535

        // ---------- global max + exp-sum (log2 domain, K = 10/ln2) ----------
        float ma = l[0];
        #pragma unroll
        for (int i = 1; i < 16; i++) ma = fmaxf(ma, l[i]);
        ma = warp_max(ma);
        const float maK = ma * KSC;
        float ea = 0.0f;
        #pragma unroll
        for (int i = 0; i < 16; i++) ea += ex2f_(fmaf(l[i], KSC, -maK));
        ea = warp_sum(ea);

        // ---------- compact positives via prefix scan (deterministic) ----------
        const int c = __popc(pm);
        int inc = c;
        #pragma unroll
        for (int j = 1; j < 32; j <<= 1) {
            int o = __shfl_up_sync(FULL, inc, j);
            if (lane >= j) inc += o;
        }
        const int P  = __shfl_sync(FULL, inc, 31);
        const int kg = min(LLEN - P, 32);
        float* pl = smp[wid];
        int off = inc - c;
        #pragma unroll
        for (int i = 0; i < 16; i++)
            if ((pm >> i) & 1) pl[off++] = l[i];
        if (lane < 4) pl[P + lane] = 1e30f;  // pad: softplus contributes exactly 0
        __syncwarp();

        // ---------- positive exp-sum from compacted list (shared max ma) ----------
        float ep = 0.0f;
        for (int r = lane; r < P; r += 32) ep += ex2f_(fmaf(pl[r], KSC, -maK));
        ep = warp_sum(ep);

        // ---------- top-32 negatives ----------
        #pragma unroll
        for (int i = 0; i < 16; i++) l[i] = ((pm >> i) & 1) ? NEGV : l[i];
        sort8(l); sort8(l + 8);
        #pragma unroll
        for (int i = 0; i < 8; i++) ce(l[15 - i], l[i]);   // halver: top-8 in l[0..7]
        float bmax = l[8];
        #pragma unroll
        for (int i = 9; i < 16; i++) bmax = fmaxf(bmax, l[i]);

        rowsort8(l, lane);
        float hard = mergetree8(l, lane);                  // candidate top-32, asc
        const float t32 = __shfl_sync(FULL, hard, 0);
        if (__any_sync(FULL, bmax > t32)) {                // exact fallback (ties ok)
            rowsort8(l + 8, lane);
            float b32 = mergetree8(l + 8, lane);
            hard = fmaxf(hard, __shfl_sync(FULL, b32, 31 - lane));
        }

        // ---------- pairwise softplus: 5 inst/pair, padded fixed-trip loop ----------
        // z <= ~17 here so 2^z cannot overflow; NEGV/pad lanes give exactly 0.
        const float hbz = fmaf(hard, INVLN2, 0.5f * INVLN2);
        float zsum = 0.0f;
        const int PT = (P + 3) & ~3;
        for (int p = 0; p < PT; p += 4) {
            float4 q = *(const float4*)&pl[p];
            zsum += lg2f_(1.0f + ex2f_(fmaf(q.x, -INVLN2, hbz)));
            zsum += lg2f_(1.0f + ex2f_(fmaf(q.y, -INVLN2, hbz)));
            zsum += lg2f_(1.0f + ex2f_(fmaf(q.z, -INVLN2, hbz)));
            zsum += lg2f_(1.0f + ex2f_(fmaf(q.w, -INVLN2, hbz)));
        }
        zsum = warp_sum(zsum);

        if (lane == 0) {
            bool  hasp    = (P > 0);
            float lw      = hasp ? LN2 * (lg2f_(ea) - lg2f_(ep)) : 0.0f;
            bool  act     = hasp && (kg > 0);
            float contrib = act ? (LN2 * zsum) / fmaxf((float)P * (float)kg, 1.0f) : 0.0f;
            my_part = make_float4(lw, hasp ? 1.0f : 0.0f, contrib, act ? 1.0f : 0.0f);
        }
    }

    // ---------- block-level reduction of 8 warp partials ----------
    if (lane == 0) s_part[wid] = my_part;
    __syncthreads();
    if (threadIdx.x < WPB) {
        float4 v = s_part[threadIdx.x];
        #pragma unroll
        for (int j = WPB >> 1; j; j >>= 1) {
            v.x += __shfl_xor_sync(0xffu, v.x, j);
            v.y += __shfl_xor_sync(0xffu, v.y, j);
            v.z += __shfl_xor_sync(0xffu, v.z, j);
            v.w += __shfl_xor_sync(0xffu, v.w, j);
        }
        if (threadIdx.x == 0) {
            g_part[blockIdx.x] = v;
            __threadfence();
            s_last = (atomicAdd(&g_ctr, 1u) == (unsigned)(nblk - 1));
        }
    }
    __syncthreads();

    // ---------- last block: reduce per-block partials (fixed order) ----------
    if (s_last) {
        float a = 0, b = 0, c2 = 0, d = 0;
        for (int i = threadIdx.x; i < nblk; i += TPB) {
            float4 v = g_part[i];
            a += v.x; b += v.y; c2 += v.z; d += v.w;
        }
        a = warp_sum(a); b = warp_sum(b); c2 = warp_sum(c2); d = warp_sum(d);
        if (lane == 0) { s_red[0][wid] = a; s_red[1][wid] = b; s_red[2][wid] = c2; s_red[3][wid] = d; }
        __syncthreads();
        if (threadIdx.x == 0) {
            float A = 0, B = 0, C = 0, D = 0;
            #pragma unroll
            for (int w = 0; w < WPB; w++) {
                A += s_red[0][w]; B += s_red[1][w];
                C += s_red[2][w]; D += s_red[3][w];
            }
            out[0] = A / fmaxf(B, 1.0f) + 0.5f * (C / fmaxf(D, 1.0f));
            g_ctr = 0;   // reset for next replay
        }
    }
}

extern "C" void kernel_launch(void* const* d_in, const int* in_sizes, int n_in,
                              void* d_out, int out_size) {
    const float* logits  = (const float*)d_in[0];
    const float* targets = (const float*)d_in[1];
    // d_in[2] (edge_batch) / d_in[3] (num_graphs) unused: segments are
    // equal-size (512) contiguous by construction.
    const int E = in_sizes[0];
    const int G = E / LLEN;
    const int nblk = (G + WPB - 1) / WPB;

    rll_fused<<<nblk, TPB>>>(logits, targets, (float*)d_out, G, nblk);
}

// round 7
// speedup vs baseline: 3.6207x; 1.1530x over previous
#include <cuda_runtime.h>

// RetrieverListwiseHardNegLoss — warp-per-graph, fully warp-synchronous.
// R7: R5 machinery + 128-thread blocks (1024 blocks @ 8/SM -> ~1.5% wave
//     imbalance vs 15% at 256/4). redux.f32 reverted (unsupported on sm_103).

#define FULL 0xffffffffu
#define NEGV (-1e30f)

static constexpr int LLEN = 512;   // edges per graph
static constexpr int WPB  = 4;     // warps (graphs) per block
static constexpr int TPB  = WPB * 32;

static constexpr float LN2    = 0.6931471805599453f;
static constexpr float INVLN2 = 1.4426950408889634f;
static constexpr float KSC    = 14.426950408889634f;  // 10 / ln(2)

__device__ float4   g_part[4096];  // per-BLOCK partials (nblk <= 4096)
__device__ unsigned g_ctr = 0;

__device__ __forceinline__ float ex2f_(float x) { float r; asm("ex2.approx.f32 %0, %1;" : "=f"(r) : "f"(x)); return r; }
__device__ __forceinline__ float lg2f_(float x) { float r; asm("lg2.approx.f32 %0, %1;" : "=f"(r) : "f"(x)); return r; }

__device__ __forceinline__ float warp_max(float v) {
    #pragma unroll
    for (int j = 16; j; j >>= 1) v = fmaxf(v, __shfl_xor_sync(FULL, v, j));
    return v;
}
__device__ __forceinline__ float warp_sum(float v) {
    #pragma unroll
    for (int j = 16; j; j >>= 1) v += __shfl_xor_sync(FULL, v, j);
    return v;
}

// Merge two ascending sorted-32 warp lists -> ascending sorted top-32.
__device__ __forceinline__ float merge32(float a, float b, int lane) {
    float br = __shfl_sync(FULL, b, 31 - lane);
    float c  = fmaxf(a, br);
    #pragma unroll
    for (int j = 16; j; j >>= 1) {
        float o = __shfl_xor_sync(FULL, c, j);
        c = ((lane & j) == 0) ? fminf(c, o) : fmaxf(c, o);
    }
    return c;
}

__device__ __forceinline__ void ce(float& a, float& b) {
    float lo = fminf(a, b), hi = fmaxf(a, b); a = lo; b = hi;
}
// Batcher odd-even mergesort, 8 inputs ascending (19 CE).
__device__ __forceinline__ void sort8(float* w) {
    ce(w[0],w[1]); ce(w[2],w[3]); ce(w[4],w[5]); ce(w[6],w[7]);
    ce(w[0],w[2]); ce(w[1],w[3]); ce(w[4],w[6]); ce(w[5],w[7]);
    ce(w[1],w[2]); ce(w[5],w[6]);
    ce(w[0],w[4]); ce(w[1],w[5]); ce(w[2],w[6]); ce(w[3],w[7]);
    ce(w[2],w[4]); ce(w[3],w[5]);
    ce(w[1],w[2]); ce(w[3],w[4]); ce(w[5],w[6]);
}
// Full bitonic sort of 8 rows across lanes (ascending per row).
__device__ __forceinline__ void rowsort8(float* w, int lane) {
    #pragma unroll
    for (int k = 2; k <= 32; k <<= 1) {
        #pragma unroll
        for (int j = k >> 1; j; j >>= 1) {
            const bool keepmin = ((lane & j) == 0) == ((lane & k) == 0);
            #pragma unroll
            for (int i = 0; i < 8; i++) {
                float o = __shfl_xor_sync(FULL, w[i], j);
                w[i] = keepmin ? fminf(w[i], o) : fmaxf(w[i], o);
            }
        }
    }
}
// 8 ascending sorted-32 lists -> ascending sorted global top-32.
__device__ __forceinline__ float mergetree8(float* w, int lane) {
    w[0] = merge32(w[0], w[1], lane); w[1] = merge32(w[2], w[3], lane);
    w[2] = merge32(w[4], w[5], lane); w[3] = merge32(w[6], w[7], lane);
    w[0] = merge32(w[0], w[1], lane); w[1] = merge32(w[2], w[3], lane);
    return merge32(w[0], w[1], lane);
}

__global__ __launch_bounds__(TPB, 8) void rll_fused(const float* __restrict__ logits,
                                                    const float* __restrict__ targets,
                                                    float* __restrict__ out,
                                                    int G, int nblk) {
    const int lane = threadIdx.x & 31;
    const int wid  = threadIdx.x >> 5;
    const int g    = blockIdx.x * WPB + wid;

    __shared__ float  smp[WPB][LLEN + 4];  // compacted positives + pad
    __shared__ float4 s_part[WPB];
    __shared__ bool   s_last;

    float4 my_part = make_float4(0.f, 0.f, 0.f, 0.f);

    if (g < G) {
        // ---------- loads + FMA-chain positive mask (t in {0,1} exactly) ----------
        const float4* L4 = (const float4*)(logits  + (size_t)g * LLEN);
        const float4* T4 = (const float4*)(targets + (size_t)g * LLEN);
        float l[16];
        float pmf = 0.0f;
        #pragma unroll
        for (int q = 0; q < 4; q++) {
            float4 a = L4[q * 32 + lane];
            float4 t = T4[q * 32 + lane];
            l[q*4+0] = a.x; l[q*4+1] = a.y; l[q*4+2] = a.z; l[q*4+3] = a.w;
            pmf = fmaf(t.x, (float)(1u << (q*4+0)), pmf);
            pmf = fmaf(t.y, (float)(1u << (q*4+1)), pmf);
            pmf = fmaf(t.z, (float)(1u << (q*4+2)), pmf);
            pmf = fmaf(t.w, (float)(1u << (q*4+3)), pmf);
        }
        const unsigned pm = (unsigned)pmf;   // exact int <= 65535

        // ---------- global max ----------
        float ma = l[0];
        #pragma unroll
        for (int i = 1; i < 16; i++) ma = fmaxf(ma, l[i]);
        ma = warp_max(ma);
        const float maK = ma * KSC;

        // ---------- ea-sum and positive-count scan: independent SHFL chains,
        //            interleaved so their latencies overlap ----------
        float ea = 0.0f;
        #pragma unroll
        for (int i = 0; i < 16; i++) ea += ex2f_(fmaf(l[i], KSC, -maK));
        const int c = __popc(pm);
        int inc = c;
        #pragma unroll
        for (int j = 1; j < 32; j <<= 1) {
            float eo = __shfl_xor_sync(FULL, ea, j);
            int   io = __shfl_up_sync(FULL, inc, j);
            ea += eo;
            if (lane >= j) inc += io;
        }
        const int P  = __shfl_sync(FULL, inc, 31);
        const int kg = min(LLEN - P, 32);

        // ---------- compact positives into smem (deterministic ranks) ----------
        float* pl = smp[wid];
        int off = inc - c;
        #pragma unroll
        for (int i = 0; i < 16; i++)
            if ((pm >> i) & 1) pl[off++] = l[i];
        if (lane < 4) pl[P + lane] = 1e30f;  // pad: softplus contributes exactly 0
        __syncwarp();

        // ---------- positive exp-sum from compacted list (shared max ma) ----------
        float ep = 0.0f;
        for (int r = lane; r < P; r += 32) ep += ex2f_(fmaf(pl[r], KSC, -maK));
        ep = warp_sum(ep);

        // ---------- top-32 negatives ----------
        #pragma unroll
        for (int i = 0; i < 16; i++) l[i] = ((pm >> i) & 1) ? NEGV : l[i];
        sort8(l); sort8(l + 8);
        #pragma unroll
        for (int i = 0; i < 8; i++) ce(l[15 - i], l[i]);   // halver: top-8 in l[0..7]
        float bmax = l[8];
        #pragma unroll
        for (int i = 9; i < 16; i++) bmax = fmaxf(bmax, l[i]);

        rowsort8(l, lane);
        float hard = mergetree8(l, lane);                  // candidate top-32, asc
        const float t32 = __shfl_sync(FULL, hard, 0);
        if (__any_sync(FULL, bmax > t32)) {                // exact fallback (ties ok)
            rowsort8(l + 8, lane);
            float b32 = mergetree8(l + 8, lane);
            hard = fmaxf(hard, __shfl_sync(FULL, b32, 31 - lane));
        }

        // ---------- pairwise softplus: 5 inst/pair, padded fixed-trip loop ----------
        // z <= ~17 here so 2^z cannot overflow; NEGV/pad lanes give exactly 0.
        const float hbz = fmaf(hard, INVLN2, 0.5f * INVLN2);
        float zsum = 0.0f;
        const int PT = (P + 3) & ~3;
        for (int p = 0; p < PT; p += 4) {
            float4 q = *(const float4*)&pl[p];
            zsum += lg2f_(1.0f + ex2f_(fmaf(q.x, -INVLN2, hbz)));
            zsum += lg2f_(1.0f + ex2f_(fmaf(q.y, -INVLN2, hbz)));
            zsum += lg2f_(1.0f + ex2f_(fmaf(q.z, -INVLN2, hbz)));
            zsum += lg2f_(1.0f + ex2f_(fmaf(q.w, -INVLN2, hbz)));
        }
        zsum = warp_sum(zsum);

        if (lane == 0) {
            bool  hasp    = (P > 0);
            float lw      = hasp ? LN2 * (lg2f_(ea) - lg2f_(ep)) : 0.0f;
            bool  act     = hasp && (kg > 0);
            float contrib = act ? (LN2 * zsum) / fmaxf((float)P * (float)kg, 1.0f) : 0.0f;
            my_part = make_float4(lw, hasp ? 1.0f : 0.0f, contrib, act ? 1.0f : 0.0f);
        }
    }

    // ---------- block-level reduction of WPB warp partials ----------
    if (lane == 0) s_part[wid] = my_part;
    __syncthreads();
    if (threadIdx.x < WPB) {
        float4 v = s_part[threadIdx.x];
        #pragma unroll
        for (int j = WPB >> 1; j; j >>= 1) {
            v.x += __shfl_xor_sync((1u << WPB) - 1u, v.x, j);
            v.y += __shfl_xor_sync((1u << WPB) - 1u, v.y, j);
            v.z += __shfl_xor_sync((1u << WPB) - 1u, v.z, j);
            v.w += __shfl_xor_sync((1u << WPB) - 1u, v.w, j);
        }
        if (threadIdx.x == 0) {
            g_part[blockIdx.x] = v;
            __threadfence();
            s_last = (atomicAdd(&g_ctr, 1u) == (unsigned)(nblk - 1));
        }
    }
    __syncthreads();

    // ---------- last block: reduce per-block partials (fixed order) ----------
    if (s_last) {
        __shared__ float s_red[4][WPB];
        float a = 0, b = 0, c2 = 0, d = 0;
        for (int i = threadIdx.x; i < nblk; i += TPB) {
            float4 v = g_part[i];
            a += v.x; b += v.y; c2 += v.z; d += v.w;
        }
        a = warp_sum(a); b = warp_sum(b); c2 = warp_sum(c2); d = warp_sum(d);
        if (lane == 0) { s_red[0][wid] = a; s_red[1][wid] = b; s_red[2][wid] = c2; s_red[3][wid] = d; }
        __syncthreads();
        if (threadIdx.x == 0) {
            float A = 0, B = 0, C = 0, D = 0;
            #pragma unroll
            for (int w = 0; w < WPB; w++) {
                A += s_red[0][w]; B += s_red[1][w];
                C += s_red[2][w]; D += s_red[3][w];
            }
            out[0] = A / fmaxf(B, 1.0f) + 0.5f * (C / fmaxf(D, 1.0f));
            g_ctr = 0;   // reset for next replay
        }
    }
}

extern "C" void kernel_launch(void* const* d_in, const int* in_sizes, int n_in,
                              void* d_out, int out_size) {
    const float* logits  = (const float*)d_in[0];
    const float* targets = (const float*)d_in[1];
    // d_in[2] (edge_batch) / d_in[3] (num_graphs) unused: segments are
    // equal-size (512) contiguous by construction.
    const int E = in_sizes[0];
    const int G = E / LLEN;
    const int nblk = (G + WPB - 1) / WPB;

    rll_fused<<<nblk, TPB>>>(logits, targets, (float*)d_out, G, nblk);
}

// round 8
// speedup vs baseline: 3.6285x; 1.0022x over previous
#include <cuda_runtime.h>

// RetrieverListwiseHardNegLoss — warp-per-graph, fully warp-synchronous.
// R8: two-level halver top-32 selection. After the 16->8 halver the top-8 is
//     a bitonic sequence, so top-4 extraction costs 4 CEs; cross-lane sort
//     shrinks 8 rows -> 4. Nested exact-threshold fallbacks (b2max >= bmax8
//     per lane, so checks chain) keep it provably exact incl. ties.

#define FULL 0xffffffffu
#define NEGV (-1e30f)

static constexpr int LLEN = 512;   // edges per graph
static constexpr int WPB  = 4;     // warps (graphs) per block
static constexpr int TPB  = WPB * 32;

static constexpr float LN2    = 0.6931471805599453f;
static constexpr float INVLN2 = 1.4426950408889634f;
static constexpr float KSC    = 14.426950408889634f;  // 10 / ln(2)

__device__ float4   g_part[4096];  // per-BLOCK partials (nblk <= 4096)
__device__ unsigned g_ctr = 0;

__device__ __forceinline__ float ex2f_(float x) { float r; asm("ex2.approx.f32 %0, %1;" : "=f"(r) : "f"(x)); return r; }
__device__ __forceinline__ float lg2f_(float x) { float r; asm("lg2.approx.f32 %0, %1;" : "=f"(r) : "f"(x)); return r; }

__device__ __forceinline__ float warp_max(float v) {
    #pragma unroll
    for (int j = 16; j; j >>= 1) v = fmaxf(v, __shfl_xor_sync(FULL, v, j));
    return v;
}
__device__ __forceinline__ float warp_min(float v) {
    #pragma unroll
    for (int j = 16; j; j >>= 1) v = fminf(v, __shfl_xor_sync(FULL, v, j));
    return v;
}
__device__ __forceinline__ float warp_sum(float v) {
    #pragma unroll
    for (int j = 16; j; j >>= 1) v += __shfl_xor_sync(FULL, v, j);
    return v;
}

// Merge two ascending sorted-32 warp lists -> ascending sorted top-32.
__device__ __forceinline__ float merge32(float a, float b, int lane) {
    float br = __shfl_sync(FULL, b, 31 - lane);
    float c  = fmaxf(a, br);
    #pragma unroll
    for (int j = 16; j; j >>= 1) {
        float o = __shfl_xor_sync(FULL, c, j);
        c = ((lane & j) == 0) ? fminf(c, o) : fmaxf(c, o);
    }
    return c;
}

__device__ __forceinline__ void ce(float& a, float& b) {
    float lo = fminf(a, b), hi = fmaxf(a, b); a = lo; b = hi;
}
// Batcher odd-even mergesort, 8 inputs ascending (19 CE).
__device__ __forceinline__ void sort8(float* w) {
    ce(w[0],w[1]); ce(w[2],w[3]); ce(w[4],w[5]); ce(w[6],w[7]);
    ce(w[0],w[2]); ce(w[1],w[3]); ce(w[4],w[6]); ce(w[5],w[7]);
    ce(w[1],w[2]); ce(w[5],w[6]);
    ce(w[0],w[4]); ce(w[1],w[5]); ce(w[2],w[6]); ce(w[3],w[7]);
    ce(w[2],w[4]); ce(w[3],w[5]);
    ce(w[1],w[2]); ce(w[3],w[4]); ce(w[5],w[6]);
}
// Full bitonic sort of NR rows across lanes (ascending per row).
template <int NR>
__device__ __forceinline__ void rowsortN(float* w, int lane) {
    #pragma unroll
    for (int k = 2; k <= 32; k <<= 1) {
        #pragma unroll
        for (int j = k >> 1; j; j >>= 1) {
            const bool keepmin = ((lane & j) == 0) == ((lane & k) == 0);
            #pragma unroll
            for (int i = 0; i < NR; i++) {
                float o = __shfl_xor_sync(FULL, w[i], j);
                w[i] = keepmin ? fminf(w[i], o) : fmaxf(w[i], o);
            }
        }
    }
}
// 8 ascending sorted-32 lists -> ascending sorted global top-32.
__device__ __forceinline__ float mergetree8(float* w, int lane) {
    w[0] = merge32(w[0], w[1], lane); w[1] = merge32(w[2], w[3], lane);
    w[2] = merge32(w[4], w[5], lane); w[3] = merge32(w[6], w[7], lane);
    w[0] = merge32(w[0], w[1], lane); w[1] = merge32(w[2], w[3], lane);
    return merge32(w[0], w[1], lane);
}

__global__ __launch_bounds__(TPB, 8) void rll_fused(const float* __restrict__ logits,
                                                    const float* __restrict__ targets,
                                                    float* __restrict__ out,
                                                    int G, int nblk) {
    const int lane = threadIdx.x & 31;
    const int wid  = threadIdx.x >> 5;
    const int g    = blockIdx.x * WPB + wid;

    __shared__ float  smp[WPB][LLEN + 4];  // compacted positives + pad
    __shared__ float4 s_part[WPB];
    __shared__ bool   s_last;

    float4 my_part = make_float4(0.f, 0.f, 0.f, 0.f);

    if (g < G) {
        // ---------- loads + positive mask via two independent FMA chains ----------
        const float4* L4 = (const float4*)(logits  + (size_t)g * LLEN);
        const float4* T4 = (const float4*)(targets + (size_t)g * LLEN);
        float l[16];
        float pmfA = 0.0f, pmfB = 0.0f;
        #pragma unroll
        for (int q = 0; q < 4; q++) {
            float4 a = L4[q * 32 + lane];
            float4 t = T4[q * 32 + lane];
            l[q*4+0] = a.x; l[q*4+1] = a.y; l[q*4+2] = a.z; l[q*4+3] = a.w;
            pmfA = fmaf(t.x, (float)(1u << (q*4+0)), pmfA);
            pmfB = fmaf(t.y, (float)(1u << (q*4+1)), pmfB);
            pmfA = fmaf(t.z, (float)(1u << (q*4+2)), pmfA);
            pmfB = fmaf(t.w, (float)(1u << (q*4+3)), pmfB);
        }
        const unsigned pm = (unsigned)(pmfA + pmfB);   // exact int <= 65535

        // ---------- global max ----------
        float ma = l[0];
        #pragma unroll
        for (int i = 1; i < 16; i++) ma = fmaxf(ma, l[i]);
        ma = warp_max(ma);
        const float maK = ma * KSC;

        // ---------- ea-sum and positive-count scan: interleaved SHFL chains ----------
        float ea = 0.0f;
        #pragma unroll
        for (int i = 0; i < 16; i++) ea += ex2f_(fmaf(l[i], KSC, -maK));
        const int c = __popc(pm);
        int inc = c;
        #pragma unroll
        for (int j = 1; j < 32; j <<= 1) {
            float eo = __shfl_xor_sync(FULL, ea, j);
            int   io = __shfl_up_sync(FULL, inc, j);
            ea += eo;
            if (lane >= j) inc += io;
        }
        const int P  = __shfl_sync(FULL, inc, 31);
        const int kg = min(LLEN - P, 32);

        // ---------- compact positives into smem (deterministic ranks) ----------
        float* pl = smp[wid];
        int off = inc - c;
        #pragma unroll
        for (int i = 0; i < 16; i++)
            if ((pm >> i) & 1) pl[off++] = l[i];
        if (lane < 4) pl[P + lane] = 1e30f;  // pad: softplus contributes exactly 0
        __syncwarp();

        // ---------- positive exp-sum from compacted list (shared max ma) ----------
        float ep = 0.0f;
        for (int r = lane; r < P; r += 32) ep += ex2f_(fmaf(pl[r], KSC, -maK));
        ep = warp_sum(ep);

        // ---------- top-32 negatives: two-level halver ----------
        #pragma unroll
        for (int i = 0; i < 16; i++) l[i] = ((pm >> i) & 1) ? NEGV : l[i];
        sort8(l); sort8(l + 8);
        #pragma unroll
        for (int i = 0; i < 8; i++) ce(l[15 - i], l[i]);   // top-8 (BITONIC) in l[0..7]
        float bmax8 = l[8];
        #pragma unroll
        for (int i = 9; i < 16; i++) bmax8 = fmaxf(bmax8, l[i]);
        // bitonic top-8 -> top-4 multiset in l[0..3] (4 CEs)
        ce(l[4], l[0]); ce(l[5], l[1]); ce(l[6], l[2]); ce(l[7], l[3]);
        float b2max = fmaxf(fmaxf(l[4], l[5]), fmaxf(l[6], l[7]));

        rowsortN<4>(l, lane);
        float m01 = merge32(l[0], l[1], lane);
        float m23 = merge32(l[2], l[3], lane);
        float hard = fmaxf(m01, __shfl_sync(FULL, m23, 31 - lane)); // multiset
        float t32  = warp_min(hard);
        // Per lane b2max >= bmax8 (top-8 elems dominate bottom-8), so the
        // level-2 condition implies level-1: checks nest.
        if (__any_sync(FULL, b2max > t32)) {               // ~10% of warps
            rowsortN<4>(l + 4, lane);
            float m45 = merge32(l[4], l[5], lane);
            float m67 = merge32(l[6], l[7], lane);
            float mA  = merge32(m01, m23, lane);
            float mB  = merge32(m45, m67, lane);
            float mAB = merge32(mA, mB, lane);             // sorted top-32 of top-8 rows
            hard = mAB;
            if (__any_sync(FULL, bmax8 > __shfl_sync(FULL, mAB, 0))) {  // ~1e-5
                rowsortN<8>(l + 8, lane);
                float b32 = mergetree8(l + 8, lane);
                hard = fmaxf(mAB, __shfl_sync(FULL, b32, 31 - lane));
            }
        }
        // lanes beyond the negative count hold NEGV -> softplus contributes 0.

        // ---------- pairwise softplus: 5 inst/pair, padded fixed-trip loop ----------
        // z <= ~17 here so 2^z cannot overflow; NEGV/pad lanes give exactly 0.
        const float hbz = fmaf(hard, INVLN2, 0.5f * INVLN2);
        float zsum = 0.0f;
        const int PT = (P + 3) & ~3;
        #pragma unroll 2
        for (int p = 0; p < PT; p += 4) {
            float4 q = *(const float4*)&pl[p];
            zsum += lg2f_(1.0f + ex2f_(fmaf(q.x, -INVLN2, hbz)));
            zsum += lg2f_(1.0f + ex2f_(fmaf(q.y, -INVLN2, hbz)));
            zsum += lg2f_(1.0f + ex2f_(fmaf(q.z, -INVLN2, hbz)));
            zsum += lg2f_(1.0f + ex2f_(fmaf(q.w, -INVLN2, hbz)));
        }
        zsum = warp_sum(zsum);

        if (lane == 0) {
            bool  hasp    = (P > 0);
            float lw      = hasp ? LN2 * (lg2f_(ea) - lg2f_(ep)) : 0.0f;
            bool  act     = hasp && (kg > 0);
            float contrib = act ? (LN2 * zsum) / fmaxf((float)P * (float)kg, 1.0f) : 0.0f;
            my_part = make_float4(lw, hasp ? 1.0f : 0.0f, contrib, act ? 1.0f : 0.0f);
        }
    }

    // ---------- block-level reduction of WPB warp partials ----------
    if (lane == 0) s_part[wid] = my_part;
    __syncthreads();
    if (threadIdx.x < WPB) {
        float4 v = s_part[threadIdx.x];
        #pragma unroll
        for (int j = WPB >> 1; j; j >>= 1) {
            v.x += __shfl_xor_sync((1u << WPB) - 1u, v.x, j);
            v.y += __shfl_xor_sync((1u << WPB) - 1u, v.y, j);
            v.z += __shfl_xor_sync((1u << WPB) - 1u, v.z, j);
            v.w += __shfl_xor_sync((1u << WPB) - 1u, v.w, j);
        }
        if (threadIdx.x == 0) {
            g_part[blockIdx.x] = v;
            __threadfence();
            s_last = (atomicAdd(&g_ctr, 1u) == (unsigned)(nblk - 1));
        }
    }
    __syncthreads();

    // ---------- last block: reduce per-block partials (fixed order) ----------
    if (s_last) {
        __shared__ float s_red[4][WPB];
        float a = 0, b = 0, c2 = 0, d = 0;
        for (int i = threadIdx.x; i < nblk; i += TPB) {
            float4 v = g_part[i];
            a += v.x; b += v.y; c2 += v.z; d += v.w;
        }
        a = warp_sum(a); b = warp_sum(b); c2 = warp_sum(c2); d = warp_sum(d);
        if (lane == 0) { s_red[0][wid] = a; s_red[1][wid] = b; s_red[2][wid] = c2; s_red[3][wid] = d; }
        __syncthreads();
        if (threadIdx.x == 0) {
            float A = 0, B = 0, C = 0, D = 0;
            #pragma unroll
            for (int w = 0; w < WPB; w++) {
                A += s_red[0][w]; B += s_red[1][w];
                C += s_red[2][w]; D += s_red[3][w];
            }
            out[0] = A / fmaxf(B, 1.0f) + 0.5f * (C / fmaxf(D, 1.0f));
            g_ctr = 0;   // reset for next replay
        }
    }
}

extern "C" void kernel_launch(void* const* d_in, const int* in_sizes, int n_in,
                              void* d_out, int out_size) {
    const float* logits  = (const float*)d_in[0];
    const float* targets = (const float*)d_in[1];
    // d_in[2] (edge_batch) / d_in[3] (num_graphs) unused: segments are
    // equal-size (512) contiguous by construction.
    const int E = in_sizes[0];
    const int G = E / LLEN;
    const int nblk = (G + WPB - 1) / WPB;

    rll_fused<<<nblk, TPB>>>(logits, targets, (float*)d_out, G, nblk);
}